// round 7
// baseline (speedup 1.0000x reference)
#include <cuda_runtime.h>
#include <math.h>

// Problem constants
#define NB    256   // batch
#define CIN   256   // input channels
#define HW    784   // 28*28 spatial
#define DD    64    // prototype channel dim
#define PP    200   // num prototypes
#define NCLS  10

constexpr int STILE   = 128;  // spatial positions per sub-tile
constexpr int KC      = 16;   // k-chunk for GEMM1 x-staging (double-buffered)
constexpr int NCHUNK  = CIN / KC;   // 16
constexpr int THREADS = 1024;

// Shared memory layout (float offsets) — weights stored TRANSPOSED
constexpr int OFF_W1T = 0;                        // [256][64]  W1^T: [c][d]
constexpr int OFF_W2T = OFF_W1T + CIN * DD;       // [64][64]   W2^T: [d1][d2]
constexpr int OFF_PT  = OFF_W2T + DD * DD;        // [64][200]  P^T:  [c][p]
constexpr int OFF_P2  = OFF_PT  + DD * PP;        // [200]
constexpr int OFF_B1  = OFF_P2  + PP;             // [64]
constexpr int OFF_B2  = OFF_B1  + DD;             // [64]
constexpr int OFF_X2  = OFF_B2  + DD;             // [128]
constexpr int OFF_MIN = OFF_X2  + STILE;          // [200] (int bits)
constexpr int OFF_XS  = ((OFF_MIN + PP + 3) / 4) * 4;  // [2][KC][128] double-buffered
constexpr int OFF_HS  = OFF_XS + 2 * KC * STILE;  // [64][128]
constexpr int OFF_FS  = OFF_HS + DD * STILE;      // [64][128]
constexpr int SMEM_FLOATS = OFF_FS + DD * STILE;
constexpr int SMEM_BYTES  = SMEM_FLOATS * 4;      // ~217.7 KB

typedef unsigned long long u64;

// ---- packed f32x2 helpers (FFMA2 — PTX-only on sm_103a) ----
__device__ __forceinline__ u64 dup2(float v) {
    u64 r; asm("mov.b64 %0, {%1,%1};" : "=l"(r) : "f"(v)); return r;
}
__device__ __forceinline__ void fma2(u64& d, u64 a, u64 b) {
    asm("fma.rn.f32x2 %0, %1, %2, %0;" : "+l"(d) : "l"(a), "l"(b));
}
__device__ __forceinline__ float2 unpk(u64 v) {
    float lo, hi; asm("mov.b64 {%0,%1}, %2;" : "=f"(lo), "=f"(hi) : "l"(v));
    return make_float2(lo, hi);
}

__global__ __launch_bounds__(THREADS, 1)
void proto_fused_kernel(const float* __restrict__ x,
                        const float* __restrict__ W1,
                        const float* __restrict__ b1,
                        const float* __restrict__ W2,
                        const float* __restrict__ b2,
                        const float* __restrict__ proto,
                        const float* __restrict__ lastW,
                        const float* __restrict__ lastB,
                        float* __restrict__ out_logits,
                        float* __restrict__ out_mind)
{
    extern __shared__ float sm[];
    float* sW1T = sm + OFF_W1T;
    float* sW2T = sm + OFF_W2T;
    float* sPT  = sm + OFF_PT;
    float* sP2  = sm + OFF_P2;
    float* sB1  = sm + OFF_B1;
    float* sB2  = sm + OFF_B2;
    float* sX2  = sm + OFF_X2;
    float* sXS  = sm + OFF_XS;
    float* sHS  = sm + OFF_HS;
    float* sFS  = sm + OFF_FS;
    int*   sMind = (int*)(sm + OFF_MIN);

    const int tid   = threadIdx.x;
    const int n     = blockIdx.x;
    const int lane  = tid & 31;
    const int grp   = tid >> 5;          // 0..31
    const int ogrp  = grp & 7;           // 8 output groups
    const int squad = grp >> 3;          // 4 spatial quarters
    const int obase = ogrp * 8;          // 8 outputs per thread
    const int sbase = squad * 32 + lane; // 1 spatial position per thread

    // ---- Prologue: stage + transpose weights into smem ----
    {
        float* tmpBig = sHS;       // 16384 floats (HS+FS contiguous)
        float* tmpW2  = sXS;       // 4096 floats
        const float4* g1 = (const float4*)W1;
        const float4* g2 = (const float4*)W2;
        for (int i = tid; i < (DD * CIN) / 4; i += THREADS) ((float4*)tmpBig)[i] = g1[i];
        for (int i = tid; i < (DD * DD) / 4; i += THREADS)  ((float4*)tmpW2)[i]  = g2[i];
        if (tid < DD) { sB1[tid] = b1[tid]; sB2[tid] = b2[tid]; }
        if (tid < PP) sMind[tid] = 0x7F7FFFFF;   // FLT_MAX bits
        __syncthreads();
        for (int i = tid; i < DD * CIN; i += THREADS) {
            int d = i >> 8, c = i & 255;           // W1[d][c]
            sW1T[c * DD + d] = tmpBig[i];
        }
        for (int i = tid; i < DD * DD; i += THREADS) {
            int d2 = i >> 6, d1 = i & 63;          // W2[d2][d1]
            sW2T[d1 * DD + d2] = tmpW2[i];
        }
        __syncthreads();
        const float4* gp = (const float4*)proto;
        for (int i = tid; i < (PP * DD) / 4; i += THREADS) ((float4*)tmpBig)[i] = gp[i];
        __syncthreads();
        for (int i = tid; i < PP * DD; i += THREADS) {
            int p = i >> 6, c = i & 63;            // proto[p][c]
            sPT[c * PP + p] = tmpBig[i];
        }
        __syncthreads();
        if (tid < PP) {                            // ||p||^2 from P^T column
            float s = 0.f;
            #pragma unroll 8
            for (int c = 0; c < DD; c++) { float v = sPT[c * PP + tid]; s += v * v; }
            sP2[tid] = s;
        }
        __syncthreads();
    }

    const float* xg = x + (size_t)n * CIN * HW;

    // staging indices for this thread (2 elements of the 2048-float chunk)
    const int st_k0 = tid >> 7;              // 0..7
    const int st_s0 = tid & 127;
    const int st_k1 = (tid + 1024) >> 7;     // 8..15
    const int st_s1 = st_s0;

    // ---- 7 spatial sub-tiles of 128 positions ----
    for (int st = 0; st < 7; st++) {
        const int s0 = st * STILE;
        const int validCnt = HW - s0;   // >=128 except last tile (16)
        const bool sval = (sbase < validCnt);

        // ===== GEMM1: h[s][d] = relu(sum_c x[c][s]*W1[d][c] + b1[d]) =====
        u64 acc[4];
        #pragma unroll
        for (int j = 0; j < 4; j++) acc[j] = 0ull;

        // prologue: stage chunk 0 into buffer 0
        {
            const int gs = s0 + st_s0;
            float r0 = (gs < HW) ? xg[st_k0 * HW + gs] : 0.f;
            float r1 = (gs < HW) ? xg[st_k1 * HW + gs] : 0.f;
            sXS[st_k0 * STILE + st_s0] = r0;
            sXS[st_k1 * STILE + st_s1] = r1;
        }
        __syncthreads();

        for (int kc = 0; kc < NCHUNK; kc++) {
            // issue next chunk's global loads into registers (overlap with compute)
            float r0 = 0.f, r1 = 0.f;
            const bool more = (kc + 1 < NCHUNK);
            if (more) {
                const int gs = s0 + st_s0;
                if (gs < HW) {
                    r0 = xg[((kc + 1) * KC + st_k0) * HW + gs];
                    r1 = xg[((kc + 1) * KC + st_k1) * HW + gs];
                }
            }
            // compute from current buffer
            const float* cur = sXS + (kc & 1) * (KC * STILE);
            const float* wb  = sW1T + (kc * KC) * DD + obase;
            #pragma unroll
            for (int k = 0; k < KC; k++) {
                const u64 d0 = dup2(cur[k * STILE + sbase]);
                const ulonglong2 wA = *(const ulonglong2*)(wb + k * DD);
                const ulonglong2 wB = *(const ulonglong2*)(wb + k * DD + 4);
                fma2(acc[0], d0, wA.x);
                fma2(acc[1], d0, wA.y);
                fma2(acc[2], d0, wB.x);
                fma2(acc[3], d0, wB.y);
            }
            // store next chunk
            if (more) {
                float* nxt = sXS + ((kc + 1) & 1) * (KC * STILE);
                nxt[st_k0 * STILE + st_s0] = r0;
                nxt[st_k1 * STILE + st_s1] = r1;
            }
            __syncthreads();
        }
        // epilogue: +bias, relu, store h transposed [d][s]
        #pragma unroll
        for (int j = 0; j < 4; j++) {
            const int d = obase + 2 * j;
            const float2 p = unpk(acc[j]);
            sHS[d * STILE + sbase]       = fmaxf(p.x + sB1[d], 0.f);
            sHS[(d + 1) * STILE + sbase] = fmaxf(p.y + sB1[d + 1], 0.f);
        }
        if (tid < STILE) sX2[tid] = 0.f;
        __syncthreads();

        // ===== GEMM2: f = sigmoid(W2 h + b2); accumulate ||f||^2 =====
        #pragma unroll
        for (int j = 0; j < 4; j++) acc[j] = 0ull;
        {
            const float* wb = sW2T + obase;
            #pragma unroll
            for (int k = 0; k < DD; k++) {
                const u64 d0 = dup2(sHS[k * STILE + sbase]);
                const ulonglong2 wA = *(const ulonglong2*)(wb + k * DD);
                const ulonglong2 wB = *(const ulonglong2*)(wb + k * DD + 4);
                fma2(acc[0], d0, wA.x);
                fma2(acc[1], d0, wA.y);
                fma2(acc[2], d0, wB.x);
                fma2(acc[3], d0, wB.y);
            }
        }
        float xs = 0.f;
        #pragma unroll
        for (int j = 0; j < 4; j++) {
            const int d = obase + 2 * j;
            const float2 p = unpk(acc[j]);
            const float f0 = 1.f / (1.f + __expf(-(p.x + sB2[d])));
            const float f1 = 1.f / (1.f + __expf(-(p.y + sB2[d + 1])));
            xs += f0 * f0 + f1 * f1;
            sFS[d * STILE + sbase]       = f0;
            sFS[(d + 1) * STILE + sbase] = f1;
        }
        atomicAdd(&sX2[sbase], xs);
        __syncthreads();

        // ===== GEMM3: xp; dist = relu(x2 - 2 xp + p2); running min =====
        const float xv = sX2[sbase];

        for (int pc = 0; pc < 4; pc++) {
            const int pbase = pc * 64 + obase;   // warp-uniform
            if (pbase >= PP) break;
            u64 c[4];
            #pragma unroll
            for (int j = 0; j < 4; j++) c[j] = 0ull;
            const float* wp = sPT + pbase;
            #pragma unroll
            for (int k = 0; k < DD; k++) {
                const u64 d0 = dup2(sFS[k * STILE + sbase]);
                const ulonglong2 wA = *(const ulonglong2*)(wp + k * PP);
                const ulonglong2 wB = *(const ulonglong2*)(wp + k * PP + 4);
                fma2(c[0], d0, wA.x);
                fma2(c[1], d0, wA.y);
                fma2(c[2], d0, wB.x);
                fma2(c[3], d0, wB.y);
            }
            #pragma unroll
            for (int j = 0; j < 4; j++) {
                const int p = pbase + 2 * j;
                const float2 q = unpk(c[j]);
                float m0 = 3.402823466e+38f, m1 = 3.402823466e+38f;
                if (sval) {
                    m0 = fmaxf(xv - 2.f * q.x + sP2[p], 0.f);
                    m1 = fmaxf(xv - 2.f * q.y + sP2[p + 1], 0.f);
                }
                #pragma unroll
                for (int o = 16; o > 0; o >>= 1) {
                    m0 = fminf(m0, __shfl_xor_sync(0xffffffffu, m0, o));
                    m1 = fminf(m1, __shfl_xor_sync(0xffffffffu, m1, o));
                }
                if (lane == 0) {
                    atomicMin(&sMind[p],     __float_as_int(m0));
                    atomicMin(&sMind[p + 1], __float_as_int(m1));
                }
            }
        }
        __syncthreads();   // protect sXS/sHS/sFS reuse in next tile
    }

    // ---- Outputs ----
    if (tid < PP)
        out_mind[n * PP + tid] = __int_as_float(sMind[tid]);
    if (tid < NCLS * 32) {
        const int cls = tid >> 5;
        float ssum = 0.f;
        for (int p = lane; p < PP; p += 32)
            ssum += __int_as_float(sMind[p]) * lastW[cls * PP + p];
        #pragma unroll
        for (int o = 16; o > 0; o >>= 1)
            ssum += __shfl_xor_sync(0xffffffffu, ssum, o);
        if (lane == 0)
            out_logits[n * NCLS + cls] = lastB[cls] - ssum;   // act = -min_dist
    }
}

extern "C" void kernel_launch(void* const* d_in, const int* in_sizes, int n_in,
                              void* d_out, int out_size) {
    (void)in_sizes; (void)n_in; (void)out_size;
    const float* x      = (const float*)d_in[0];
    const float* W1     = (const float*)d_in[1];
    const float* b1     = (const float*)d_in[2];
    const float* W2     = (const float*)d_in[3];
    const float* b2     = (const float*)d_in[4];
    const float* proto  = (const float*)d_in[5];
    const float* lastW  = (const float*)d_in[6];
    const float* lastB  = (const float*)d_in[7];
    float* out        = (float*)d_out;
    float* out_logits = out;                 // (256,10)
    float* out_mind   = out + NB * NCLS;     // (256,200)

    cudaFuncSetAttribute(proto_fused_kernel,
                         cudaFuncAttributeMaxDynamicSharedMemorySize, SMEM_BYTES);
    proto_fused_kernel<<<NB, THREADS, SMEM_BYTES>>>(
        x, W1, b1, W2, b2, proto, lastW, lastB, out_logits, out_mind);
}

// round 11
// speedup vs baseline: 1.9291x; 1.9291x over previous
// ProtoPNet head, fully fused, WMMA fp16x2 (split hi/lo, 3-term MMA, fp32 acc).
// Base-target mma.sync (sm_70+) — legal on compute_103. One CTA per image.
#include <cuda_runtime.h>
#include <cuda_fp16.h>
#include <mma.h>
#include <cstdint>
using namespace nvcuda;

#define NB 256
#define CIN 256
#define HW 784
#define DD 64
#define PP 200
#define NCLS 10

constexpr int THREADS = 256;
constexpr int NW = 8;
constexpr int STILE = 128;
constexpr int KCH = 64;             // channels per GEMM1 chunk
constexpr int NCHUNK = CIN / KCH;   // 4
constexpr int NTILES = 7;
constexpr int LDW = 72;             // W1T/W2T leading dim (halfs)
constexpr int LDA = 72;             // A (X/h/f) leading dim (halfs)
constexpr int LDP = 216;            // P^T leading dim (halfs), 200->pad
constexpr int PPAD = 208;           // n-tiles: 13 x 16
constexpr int LDC = 20;             // CW staging leading dim (floats)

// ---- smem byte offsets ----
constexpr int OFF_W1H = 0;               // [256][72] half
constexpr int OFF_W1L = 36864;
constexpr int OFF_W2H = 73728;           // [64][72] half
constexpr int OFF_W2L = 82944;
constexpr int OFF_PTH = 92160;           // [64][216] half
constexpr int OFF_PTL = 119808;
constexpr int OFF_AH  = 147456;          // [128][72] half (X chunk / h / f)
constexpr int OFF_AL  = 165888;
constexpr int OFF_CW  = 184320;          // 8 x [16][20] float
constexpr int OFF_X2  = 194560;          // [128] float
constexpr int OFF_P2  = 195072;          // [208] float
constexpr int OFF_B1  = 195904;          // [64] float
constexpr int OFF_B2  = 196160;          // [64] float
constexpr int OFF_MIND = 196416;         // [208] int
constexpr int SMEM_BYTES = 197248;       // ~192.6 KB

using FragA = wmma::fragment<wmma::matrix_a, 16, 16, 16, __half, wmma::row_major>;
using FragB = wmma::fragment<wmma::matrix_b, 16, 16, 16, __half, wmma::row_major>;
using FragC = wmma::fragment<wmma::accumulator, 16, 16, 16, float>;

__device__ __forceinline__ void split2(float v, __half& hi, __half& lo) {
    hi = __float2half_rn(v);
    lo = __float2half_rn(v - __half2float(hi));
}

__global__ __launch_bounds__(THREADS, 1)
void proto_h2_kernel(const float* __restrict__ x,
                     const float* __restrict__ W1,
                     const float* __restrict__ b1,
                     const float* __restrict__ W2,
                     const float* __restrict__ b2,
                     const float* __restrict__ proto,
                     const float* __restrict__ lastW,
                     const float* __restrict__ lastB,
                     float* __restrict__ out_logits,
                     float* __restrict__ out_mind)
{
    extern __shared__ char smem[];
    __half* sW1H = (__half*)(smem + OFF_W1H);
    __half* sW1L = (__half*)(smem + OFF_W1L);
    __half* sW2H = (__half*)(smem + OFF_W2H);
    __half* sW2L = (__half*)(smem + OFF_W2L);
    __half* sPTH = (__half*)(smem + OFF_PTH);
    __half* sPTL = (__half*)(smem + OFF_PTL);
    __half* sAH  = (__half*)(smem + OFF_AH);
    __half* sAL  = (__half*)(smem + OFF_AL);
    float*  sCWb = (float*)(smem + OFF_CW);
    float*  sX2  = (float*)(smem + OFF_X2);
    float*  sP2  = (float*)(smem + OFF_P2);
    float*  sB1  = (float*)(smem + OFF_B1);
    float*  sB2  = (float*)(smem + OFF_B2);
    int*    sMind = (int*)(smem + OFF_MIND);

    const int tid  = threadIdx.x;
    const int lane = tid & 31;
    const int warp = tid >> 5;          // 0..7, owns spatial rows [warp*16,+16)
    const int n    = blockIdx.x;

    // ---- Prologue: weights transposed + hi/lo split into smem ----
    for (int i = tid; i < DD * CIN; i += THREADS) {      // W1[d][c] -> [c][d]
        int d = i >> 8, c = i & 255;
        __half hi, lo; split2(W1[i], hi, lo);
        sW1H[c * LDW + d] = hi; sW1L[c * LDW + d] = lo;
    }
    for (int i = tid; i < DD * DD; i += THREADS) {       // W2[d2][d1] -> [d1][d2]
        int d2 = i >> 6, d1 = i & 63;
        __half hi, lo; split2(W2[i], hi, lo);
        sW2H[d1 * LDW + d2] = hi; sW2L[d1 * LDW + d2] = lo;
    }
    for (int i = tid; i < PP * DD; i += THREADS) {       // proto[p][c] -> [c][p]
        int p = i >> 6, c = i & 63;
        __half hi, lo; split2(proto[i], hi, lo);
        sPTH[c * LDP + p] = hi; sPTL[c * LDP + p] = lo;
    }
    for (int i = tid; i < DD * (LDP - PP); i += THREADS) {  // zero pad cols
        int c = i / (LDP - PP), p = PP + i % (LDP - PP);
        sPTH[c * LDP + p] = __float2half(0.f);
        sPTL[c * LDP + p] = __float2half(0.f);
    }
    if (tid < DD) { sB1[tid] = b1[tid]; sB2[tid] = b2[tid]; }
    if (tid < PPAD) {
        float s = 0.f;
        if (tid < PP) {
            #pragma unroll 8
            for (int c = 0; c < DD; c++) { float v = proto[tid * DD + c]; s += v * v; }
        }
        sP2[tid] = s;
        sMind[tid] = 0x7F7FFFFF;
    }
    __syncthreads();

    const float* xg = x + (size_t)n * CIN * HW;
    float* cw = sCWb + warp * (16 * LDC);
    const int col = lane & 15;
    const int r0  = (lane >> 4) * 8;

    for (int st = 0; st < NTILES; st++) {
        const int s0 = st * STILE;
        const int validCnt = HW - s0;

        // ===== GEMM1: C1[128,64] = X[128,256] * W1T, hi/lo 3-term =====
        FragC c1[4];
        #pragma unroll
        for (int j = 0; j < 4; j++) wmma::fill_fragment(c1[j], 0.f);

        for (int ch = 0; ch < NCHUNK; ch++) {
            __syncthreads();    // A tiles free (prev readers done)
            const int kbase = ch * KCH;
            #pragma unroll
            for (int it = 0; it < (KCH * STILE) / THREADS; it++) {  // 32
                int idx = it * THREADS + tid;
                int c = idx >> 7, s = idx & 127;
                int gs = s0 + s;
                float v = (gs < HW) ? xg[(kbase + c) * HW + gs] : 0.f;
                __half hi, lo; split2(v, hi, lo);
                sAH[s * LDA + c] = hi; sAL[s * LDA + c] = lo;
            }
            __syncthreads();
            FragA ah[4], al[4];
            #pragma unroll
            for (int ks = 0; ks < 4; ks++) {
                wmma::load_matrix_sync(ah[ks], sAH + (warp * 16) * LDA + ks * 16, LDA);
                wmma::load_matrix_sync(al[ks], sAL + (warp * 16) * LDA + ks * 16, LDA);
            }
            #pragma unroll
            for (int ks = 0; ks < 4; ks++) {
                const int kr = kbase + ks * 16;
                #pragma unroll
                for (int nt = 0; nt < 4; nt++) {
                    FragB bh, bl;
                    wmma::load_matrix_sync(bh, sW1H + kr * LDW + nt * 16, LDW);
                    wmma::mma_sync(c1[nt], ah[ks], bh, c1[nt]);
                    wmma::mma_sync(c1[nt], al[ks], bh, c1[nt]);
                    wmma::load_matrix_sync(bl, sW1L + kr * LDW + nt * 16, LDW);
                    wmma::mma_sync(c1[nt], ah[ks], bl, c1[nt]);
                }
            }
        }
        // epilogue 1 (per-warp, own rows): h = relu(v+b1) -> hi/lo into A tiles
        #pragma unroll
        for (int nt = 0; nt < 4; nt++) {
            wmma::store_matrix_sync(cw, c1[nt], LDC, wmma::mem_row_major);
            __syncwarp();
            const int d = nt * 16 + col;
            #pragma unroll
            for (int j = 0; j < 8; j++) {
                const int r = r0 + j;
                float v = fmaxf(cw[r * LDC + col] + sB1[d], 0.f);
                __half hi, lo; split2(v, hi, lo);
                sAH[(warp * 16 + r) * LDA + d] = hi;
                sAL[(warp * 16 + r) * LDA + d] = lo;
            }
            __syncwarp();
        }

        // ===== GEMM2: C2 = h * W2T (K=64), hi/lo 3-term =====
        FragC c2[4];
        #pragma unroll
        for (int j = 0; j < 4; j++) wmma::fill_fragment(c2[j], 0.f);
        {
            FragA ah[4], al[4];
            #pragma unroll
            for (int ks = 0; ks < 4; ks++) {
                wmma::load_matrix_sync(ah[ks], sAH + (warp * 16) * LDA + ks * 16, LDA);
                wmma::load_matrix_sync(al[ks], sAL + (warp * 16) * LDA + ks * 16, LDA);
            }
            #pragma unroll
            for (int ks = 0; ks < 4; ks++) {
                #pragma unroll
                for (int nt = 0; nt < 4; nt++) {
                    FragB bh, bl;
                    wmma::load_matrix_sync(bh, sW2H + (ks * 16) * LDW + nt * 16, LDW);
                    wmma::mma_sync(c2[nt], ah[ks], bh, c2[nt]);
                    wmma::mma_sync(c2[nt], al[ks], bh, c2[nt]);
                    wmma::load_matrix_sync(bl, sW2L + (ks * 16) * LDW + nt * 16, LDW);
                    wmma::mma_sync(c2[nt], ah[ks], bl, c2[nt]);
                }
            }
        }
        // epilogue 2: f = sigmoid(v+b2) -> hi/lo into A tiles (own rows)
        #pragma unroll
        for (int nt = 0; nt < 4; nt++) {
            wmma::store_matrix_sync(cw, c2[nt], LDC, wmma::mem_row_major);
            __syncwarp();
            const int d = nt * 16 + col;
            #pragma unroll
            for (int j = 0; j < 8; j++) {
                const int r = r0 + j;
                float v = cw[r * LDC + col] + sB2[d];
                float f = 1.f / (1.f + __expf(-v));
                __half hi, lo; split2(f, hi, lo);
                sAH[(warp * 16 + r) * LDA + d] = hi;
                sAL[(warp * 16 + r) * LDA + d] = lo;
            }
            __syncwarp();
        }
        __syncthreads();

        // ---- x2[r] = sum_d f_eff^2 (f_eff = hi+lo) ----
        {
            const int r = tid >> 1, co = (tid & 1) * 32;
            float s2 = 0.f;
            #pragma unroll 8
            for (int j = 0; j < 32; j++) {
                float f = __half2float(sAH[r * LDA + co + j]) +
                          __half2float(sAL[r * LDA + co + j]);
                s2 += f * f;
            }
            s2 += __shfl_xor_sync(0xffffffffu, s2, 1);
            if ((tid & 1) == 0) sX2[r] = s2;
        }
        __syncthreads();

        // ===== GEMM3: C3[128,208] = f * PT (K=64), per 16-col tile =====
        {
            FragA ah[4], al[4];
            #pragma unroll
            for (int ks = 0; ks < 4; ks++) {
                wmma::load_matrix_sync(ah[ks], sAH + (warp * 16) * LDA + ks * 16, LDA);
                wmma::load_matrix_sync(al[ks], sAL + (warp * 16) * LDA + ks * 16, LDA);
            }
            for (int nt = 0; nt < PPAD / 16; nt++) {   // 13
                FragC c3;
                wmma::fill_fragment(c3, 0.f);
                #pragma unroll
                for (int ks = 0; ks < 4; ks++) {
                    FragB bh, bl;
                    wmma::load_matrix_sync(bh, sPTH + (ks * 16) * LDP + nt * 16, LDP);
                    wmma::mma_sync(c3, ah[ks], bh, c3);
                    wmma::mma_sync(c3, al[ks], bh, c3);
                    wmma::load_matrix_sync(bl, sPTL + (ks * 16) * LDP + nt * 16, LDP);
                    wmma::mma_sync(c3, ah[ks], bl, c3);
                }
                wmma::store_matrix_sync(cw, c3, LDC, wmma::mem_row_major);
                __syncwarp();
                const int p = nt * 16 + col;
                const float pn2 = sP2[p];
                float mn = 3.402823466e+38f;
                #pragma unroll
                for (int j = 0; j < 8; j++) {
                    const int r = r0 + j;
                    if (warp * 16 + r < validCnt) {
                        float v = cw[r * LDC + col];
                        mn = fminf(mn, fmaxf(sX2[warp * 16 + r] - 2.f * v + pn2, 0.f));
                    }
                }
                mn = fminf(mn, __shfl_xor_sync(0xffffffffu, mn, 16));
                if (lane < 16 && p < PP)
                    atomicMin(sMind + p, __float_as_int(mn));
                __syncwarp();
            }
        }
        // next tile's chunk-staging __syncthreads protects A-tile reuse
    }
    __syncthreads();

    // ---- Outputs ----
    if (tid < PP)
        out_mind[n * PP + tid] = __int_as_float(sMind[tid]);
    // logits: warp per class, strided — covers all NCLS=10 with 8 warps
    for (int cls = warp; cls < NCLS; cls += NW) {
        float ssum = 0.f;
        for (int p = lane; p < PP; p += 32)
            ssum += __int_as_float(sMind[p]) * lastW[cls * PP + p];
        #pragma unroll
        for (int o = 16; o > 0; o >>= 1)
            ssum += __shfl_xor_sync(0xffffffffu, ssum, o);
        if (lane == 0)
            out_logits[n * NCLS + cls] = lastB[cls] - ssum;   // act = -min_dist
    }
}

extern "C" void kernel_launch(void* const* d_in, const int* in_sizes, int n_in,
                              void* d_out, int out_size) {
    (void)in_sizes; (void)n_in; (void)out_size;
    const float* x     = (const float*)d_in[0];
    const float* W1    = (const float*)d_in[1];
    const float* b1    = (const float*)d_in[2];
    const float* W2    = (const float*)d_in[3];
    const float* b2    = (const float*)d_in[4];
    const float* proto = (const float*)d_in[5];
    const float* lastW = (const float*)d_in[6];
    const float* lastB = (const float*)d_in[7];
    float* out        = (float*)d_out;
    float* out_logits = out;                 // (256,10)
    float* out_mind   = out + NB * NCLS;     // (256,200)

    cudaFuncSetAttribute(proto_h2_kernel,
                         cudaFuncAttributeMaxDynamicSharedMemorySize, SMEM_BYTES);
    proto_h2_kernel<<<NB, THREADS, SMEM_BYTES>>>(
        x, W1, b1, W2, b2, proto, lastW, lastB, out_logits, out_mind);
}